// round 1
// baseline (speedup 1.0000x reference)
#include <cuda_runtime.h>

// PairwiseScore — fp32 baseline with algebraic decomposition + packed f32x2 FMA.
//
// pairs@W1 = i_g@W1a + j_g@W1b + (i_g*j_g)@W1c + phi@W1d
//   - AB[n]  : per-mention precompute of g_i[n]@W1a (cols 0..149) and g_i[n]@W1b (cols 160..309)
//   - Dt/Gt/St: tiny phi lookup tables (b1 folded into Dt)
//   - main kernel: bilinear GEMM per 64-pair tile + fused 2-layer MLP epilogue.

typedef unsigned long long ull;

#define GI   1220
#define HID  150
#define NMAX 50000
#define CPAD 160      // padded hidden width (cols 150..159 are zero)
#define ABS  320      // AB row stride in floats (A part @0, B part @160)
#define KC   16       // K-chunk

// -------- device scratch (no allocations allowed) --------
__device__ float d_AB[(size_t)NMAX * ABS];   // 64 MB
__device__ float d_Wab[GI * ABS];            // packed [W1a | pad | W1b | pad]
__device__ float d_Wc[GI * CPAD];            // W1c zero-padded to 160 cols
__device__ float d_Dt[9 * CPAD];             // dist table (+b1)
__device__ float d_Gt[8 * CPAD];             // genre table
__device__ float d_St[3 * CPAD];             // speaker table

// -------- packed f32x2 helpers --------
__device__ __forceinline__ void fma2(ull &d, ull a, ull b) {
    asm("fma.rn.f32x2 %0, %1, %2, %0;" : "+l"(d) : "l"(a), "l"(b));
}
__device__ __forceinline__ ull bcast2(float x) {
    ull r; asm("mov.b64 %0, {%1, %1};" : "=l"(r) : "f"(x)); return r;
}
__device__ __forceinline__ ull pk(float x, float y) {
    ull r; asm("mov.b64 %0, {%1, %2};" : "=l"(r) : "f"(x), "f"(y)); return r;
}
__device__ __forceinline__ float2 unpk(ull v) {
    float2 r; asm("mov.b64 {%0, %1}, %2;" : "=f"(r.x), "=f"(r.y) : "l"(v)); return r;
}

// ===================== weight prep =====================

__global__ void prep_weights(const float* __restrict__ W1) {
    int k = blockIdx.x;      // 0..GI-1
    int c = threadIdx.x;     // 0..319
    float v = 0.f;
    if (c < HID)                       v = W1[k * HID + c];
    else if (c >= CPAD && c < CPAD+HID) v = W1[(GI + k) * HID + (c - CPAD)];
    d_Wab[k * ABS + c] = v;
    if (c < CPAD)
        d_Wc[k * CPAD + c] = (c < HID) ? W1[(2 * GI + k) * HID + c] : 0.f;
}

__global__ void prep_tabs(const float* __restrict__ de, const float* __restrict__ ge,
                          const float* __restrict__ se, const float* __restrict__ W1,
                          const float* __restrict__ b1) {
    int c = threadIdx.x;     // 0..159
    for (int d = 0; d < 9; ++d) {
        float v = 0.f;
        if (c < HID) {
            v = b1[c];
            for (int t = 0; t < 20; ++t) v += de[d*20 + t] * W1[(3*GI + t) * HID + c];
        }
        d_Dt[d * CPAD + c] = v;
    }
    for (int g = 0; g < 8; ++g) {
        float v = 0.f;
        if (c < HID)
            for (int t = 0; t < 20; ++t) v += ge[g*20 + t] * W1[(3*GI + 20 + t) * HID + c];
        d_Gt[g * CPAD + c] = v;
    }
    for (int s = 0; s < 3; ++s) {
        float v = 0.f;
        if (c < HID)
            for (int t = 0; t < 20; ++t) v += se[s*20 + t] * W1[(3*GI + 40 + t) * HID + c];
        d_St[s * CPAD + c] = v;
    }
}

// ===================== AB precompute GEMM: [64 x 1220] @ [1220 x 320] =====================

__global__ __launch_bounds__(256) void gemm_ab(const float* __restrict__ g, int N) {
    __shared__ ull   Ws[KC * 160];   // 16 x 160 colpairs = 20 KB
    __shared__ float Qs[KC * 65];    // padded stride 65

    int t  = threadIdx.x;
    int tx = t & 15, ty = t >> 4;    // ty also serves as producer kk
    int ty4 = ty * 4;
    int n0 = blockIdx.x * 64;

    int pp = t >> 2, q = t & 3;
    int nrow = n0 + pp; if (nrow >= N) nrow = N - 1;
    const float* grow = g + (size_t)nrow * GI;

    ull acc[4][10];
    #pragma unroll
    for (int j = 0; j < 4; ++j)
        #pragma unroll
        for (int c = 0; c < 10; ++c) acc[j][c] = 0ull;

    const ull* Wab64 = (const ull*)d_Wab;   // row stride 160 colpairs

    for (int k0 = 0; k0 < GI; k0 += KC) {
        __syncthreads();
        // stage W chunk [16 x 320]
        {
            int k = k0 + ty;
            #pragma unroll
            for (int i = 0; i < 10; ++i) {
                ull w = 0ull;
                if (k < GI) w = Wab64[(size_t)k * 160 + tx + 16*i];
                Ws[ty * 160 + tx + 16*i] = w;
            }
        }
        // stage Q chunk [16 x 64] (transposed, stride 65)
        {
            int kb = k0 + 4*q;
            float4 v;
            if (kb + 3 < GI) v = *(const float4*)(grow + kb);
            else {
                v.x = (kb+0 < GI) ? grow[kb+0] : 0.f;
                v.y = (kb+1 < GI) ? grow[kb+1] : 0.f;
                v.z = (kb+2 < GI) ? grow[kb+2] : 0.f;
                v.w = (kb+3 < GI) ? grow[kb+3] : 0.f;
            }
            Qs[(4*q+0)*65 + pp] = v.x;
            Qs[(4*q+1)*65 + pp] = v.y;
            Qs[(4*q+2)*65 + pp] = v.z;
            Qs[(4*q+3)*65 + pp] = v.w;
        }
        __syncthreads();
        #pragma unroll
        for (int kk = 0; kk < KC; ++kk) {
            ull qq[4];
            #pragma unroll
            for (int j = 0; j < 4; ++j) qq[j] = bcast2(Qs[kk*65 + ty4 + j]);
            #pragma unroll
            for (int c = 0; c < 10; ++c) {
                ull w = Ws[kk*160 + tx + 16*c];
                #pragma unroll
                for (int j = 0; j < 4; ++j) fma2(acc[j][c], qq[j], w);
            }
        }
    }
    __syncthreads();

    ull* AB64 = (ull*)d_AB;   // row stride 160 colpairs
    #pragma unroll
    for (int j = 0; j < 4; ++j) {
        int n = n0 + ty4 + j;
        if (n < N) {
            #pragma unroll
            for (int c = 0; c < 10; ++c)
                AB64[(size_t)n * 160 + tx + 16*c] = acc[j][c];
        }
    }
}

// ===================== main: bilinear GEMM + fused MLP =====================

__global__ __launch_bounds__(256) void pair_main(
    const float* __restrict__ g,  const float* __restrict__ ms,
    const float* __restrict__ W2, const float* __restrict__ b2,
    const float* __restrict__ W3, const float* __restrict__ b3,
    const int* __restrict__ mid,  const int* __restrict__ aid,
    const int* __restrict__ did,  const int* __restrict__ gid,
    const int* __restrict__ sid,
    float* __restrict__ out, int P)
{
    extern __shared__ unsigned char smem_raw[];
    ull*   Ws   = (ull*)smem_raw;                                  // 16*80 ull = 10240 B
    float* QH   = (float*)(smem_raw + 10240);                      // Qs[16*65] then h1s[64*160]
    int*   sm_m = (int*)(smem_raw + 10240 + 64*CPAD*4);
    int*   sm_a = sm_m + 64;
    int*   sm_d = sm_a + 64;
    int*   sm_g = sm_d + 64;
    int*   sm_s = sm_g + 64;
    float* w3s  = (float*)(sm_s + 64);                             // [160]

    int t  = threadIdx.x;
    int tx = t & 15, ty = t >> 4;
    int ty4 = ty * 4;
    int p0 = blockIdx.x * 64;

    if (t < 64) {
        int p = p0 + t;
        int m = 0, a = 0, dd = 0, gg = 0, ss = 0;
        if (p < P) { m = mid[p]; a = aid[p]; dd = did[p]; gg = gid[p]; ss = sid[p]; }
        sm_m[t] = m; sm_a[t] = a; sm_d[t] = dd; sm_g[t] = gg; sm_s[t] = ss;
    }
    if (t < CPAD) w3s[t] = (t < HID) ? W3[t] : 0.f;
    __syncthreads();

    int pp = t >> 2, q = t & 3;
    const float* irow = g + (size_t)sm_m[pp] * GI;
    const float* jrow = g + (size_t)sm_a[pp] * GI;

    // ---- layer 1: bilinear (i*j) @ W1c over K=1220 ----
    ull acc[4][5];
    #pragma unroll
    for (int j = 0; j < 4; ++j)
        #pragma unroll
        for (int c = 0; c < 5; ++c) acc[j][c] = 0ull;

    const ull* Wc64 = (const ull*)d_Wc;   // row stride 80 colpairs

    for (int k0 = 0; k0 < GI; k0 += KC) {
        __syncthreads();
        {
            int k = k0 + ty;
            #pragma unroll
            for (int i = 0; i < 5; ++i) {
                ull w = 0ull;
                if (k < GI) w = Wc64[(size_t)k * 80 + tx + 16*i];
                Ws[ty * 80 + tx + 16*i] = w;
            }
        }
        {
            int kb = k0 + 4*q;
            float4 x, y;
            if (kb + 3 < GI) {
                x = *(const float4*)(irow + kb);
                y = *(const float4*)(jrow + kb);
            } else {
                x.x = (kb+0 < GI) ? irow[kb+0] : 0.f;  y.x = (kb+0 < GI) ? jrow[kb+0] : 0.f;
                x.y = (kb+1 < GI) ? irow[kb+1] : 0.f;  y.y = (kb+1 < GI) ? jrow[kb+1] : 0.f;
                x.z = (kb+2 < GI) ? irow[kb+2] : 0.f;  y.z = (kb+2 < GI) ? jrow[kb+2] : 0.f;
                x.w = (kb+3 < GI) ? irow[kb+3] : 0.f;  y.w = (kb+3 < GI) ? jrow[kb+3] : 0.f;
            }
            QH[(4*q+0)*65 + pp] = x.x * y.x;
            QH[(4*q+1)*65 + pp] = x.y * y.y;
            QH[(4*q+2)*65 + pp] = x.z * y.z;
            QH[(4*q+3)*65 + pp] = x.w * y.w;
        }
        __syncthreads();
        #pragma unroll
        for (int kk = 0; kk < KC; ++kk) {
            ull qq[4];
            #pragma unroll
            for (int j = 0; j < 4; ++j) qq[j] = bcast2(QH[kk*65 + ty4 + j]);
            #pragma unroll
            for (int c = 0; c < 5; ++c) {
                ull w = Ws[kk*80 + tx + 16*c];
                #pragma unroll
                for (int j = 0; j < 4; ++j) fma2(acc[j][c], qq[j], w);
            }
        }
    }
    __syncthreads();

    // ---- epilogue 1: h1 = relu(bilinear + AB[m] + AB[a] + Dt + Gt + St) -> SMEM ----
    {
        const float2* AB2 = (const float2*)d_AB;   // row stride 160 float2
        const float2* Dt2 = (const float2*)d_Dt;   // row stride 80 float2
        const float2* Gt2 = (const float2*)d_Gt;
        const float2* St2 = (const float2*)d_St;
        #pragma unroll
        for (int j = 0; j < 4; ++j) {
            int r = ty4 + j;
            const float2* am = AB2 + (size_t)sm_m[r] * 160;
            const float2* bm = AB2 + (size_t)sm_a[r] * 160 + 80;
            const float2* dp = Dt2 + sm_d[r] * 80;
            const float2* gp = Gt2 + sm_g[r] * 80;
            const float2* sp = St2 + sm_s[r] * 80;
            #pragma unroll
            for (int c = 0; c < 5; ++c) {
                int cp = tx + 16*c;
                float2 v  = unpk(acc[j][c]);
                float2 t1 = am[cp], t2 = bm[cp], t3 = dp[cp], t4 = gp[cp], t5 = sp[cp];
                v.x = fmaxf(v.x + t1.x + t2.x + t3.x + t4.x + t5.x, 0.f);
                v.y = fmaxf(v.y + t1.y + t2.y + t3.y + t4.y + t5.y, 0.f);
                *(float2*)(QH + r * CPAD + 2*cp) = v;
            }
        }
    }

    // ---- layer 2: h2pre = h1 @ W2 ----
    ull acc2[4][5];
    #pragma unroll
    for (int j = 0; j < 4; ++j)
        #pragma unroll
        for (int c = 0; c < 5; ++c) acc2[j][c] = 0ull;

    for (int k0 = 0; k0 < CPAD; k0 += KC) {   // 10 chunks (k>=150 is zero-padded)
        __syncthreads();
        {
            int k = k0 + ty;
            #pragma unroll
            for (int i = 0; i < 5; ++i) {
                int cp = tx + 16*i, c0 = 2*cp;
                ull w = 0ull;
                if (k < HID) {
                    float lo = (c0   < HID) ? W2[k*HID + c0    ] : 0.f;
                    float hi = (c0+1 < HID) ? W2[k*HID + c0 + 1] : 0.f;
                    w = pk(lo, hi);
                }
                Ws[ty * 80 + cp] = w;
            }
        }
        __syncthreads();
        #pragma unroll
        for (int kk = 0; kk < KC; ++kk) {
            ull qq[4];
            #pragma unroll
            for (int j = 0; j < 4; ++j) qq[j] = bcast2(QH[(ty4+j)*CPAD + k0 + kk]);
            #pragma unroll
            for (int c = 0; c < 5; ++c) {
                ull w = Ws[kk*80 + tx + 16*c];
                #pragma unroll
                for (int j = 0; j < 4; ++j) fma2(acc2[j][c], qq[j], w);
            }
        }
    }

    // ---- epilogue 2: relu(h2pre + b2) @ W3 + b3 + ms[m] + ms[a] ----
    float b3v = b3[0];
    float part[4] = {0.f, 0.f, 0.f, 0.f};
    #pragma unroll
    for (int c = 0; c < 5; ++c) {
        int c0 = 2 * (tx + 16*c);
        float w3a = w3s[c0], w3b = w3s[c0 + 1];
        float b2a = (c0   < HID) ? b2[c0    ] : 0.f;
        float b2b = (c0+1 < HID) ? b2[c0 + 1] : 0.f;
        #pragma unroll
        for (int j = 0; j < 4; ++j) {
            float2 v = unpk(acc2[j][c]);
            part[j] += fmaxf(v.x + b2a, 0.f) * w3a + fmaxf(v.y + b2b, 0.f) * w3b;
        }
    }
    #pragma unroll
    for (int j = 0; j < 4; ++j) {
        #pragma unroll
        for (int off = 8; off > 0; off >>= 1)
            part[j] += __shfl_xor_sync(0xffffffffu, part[j], off);
    }
    if (tx == 0) {
        #pragma unroll
        for (int j = 0; j < 4; ++j) {
            int p = p0 + ty4 + j;
            if (p < P)
                out[p] = part[j] + b3v + ms[sm_m[ty4 + j]] + ms[sm_a[ty4 + j]];
        }
    }
}

// ===================== launch =====================

extern "C" void kernel_launch(void* const* d_in, const int* in_sizes, int n_in,
                              void* d_out, int out_size)
{
    const float* g_i = (const float*)d_in[0];
    const float* ms  = (const float*)d_in[1];
    const float* de  = (const float*)d_in[2];
    const float* ge  = (const float*)d_in[3];
    const float* se  = (const float*)d_in[4];
    const float* W1  = (const float*)d_in[5];
    const float* b1  = (const float*)d_in[6];
    const float* W2  = (const float*)d_in[7];
    const float* b2  = (const float*)d_in[8];
    const float* W3  = (const float*)d_in[9];
    const float* b3  = (const float*)d_in[10];
    const int*   mid = (const int*)d_in[11];
    const int*   aid = (const int*)d_in[12];
    const int*   did = (const int*)d_in[13];
    const int*   gid = (const int*)d_in[14];
    const int*   sid = (const int*)d_in[15];

    int N = in_sizes[0] / GI;
    if (N > NMAX) N = NMAX;
    int P = in_sizes[11];
    float* out = (float*)d_out;

    prep_weights<<<GI, 320>>>(W1);
    prep_tabs<<<1, CPAD>>>(de, ge, se, W1, b1);
    gemm_ab<<<(N + 63) / 64, 256>>>(g_i, N);

    int smem = 10240 + 64*CPAD*4 + 5*64*4 + CPAD*4;   // 53120 B
    cudaFuncSetAttribute(pair_main, cudaFuncAttributeMaxDynamicSharedMemorySize, smem);
    pair_main<<<(P + 63) / 64, 256, smem>>>(g_i, ms, W2, b2, W3, b3,
                                            mid, aid, did, gid, sid, out, P);
}

// round 2
// speedup vs baseline: 1.0005x; 1.0005x over previous
#include <cuda_runtime.h>

// PairwiseScore — fp32 baseline with algebraic decomposition + packed f32x2 FMA.
//
// pairs@W1 = i_g@W1a + j_g@W1b + (i_g*j_g)@W1c + phi@W1d
//   - AB[n]  : per-mention precompute of g_i[n]@W1a (cols 0..149) and g_i[n]@W1b (cols 160..309)
//   - Dt/Gt/St: tiny phi lookup tables (b1 folded into Dt)
//   - main kernel: bilinear GEMM per 64-pair tile + fused 2-layer MLP epilogue.

typedef unsigned long long ull;

#define GI   1220
#define HID  150
#define NMAX 50000
#define CPAD 160      // padded hidden width (cols 150..159 are zero)
#define ABS  320      // AB row stride in floats (A part @0, B part @160)
#define KC   16       // K-chunk

// -------- device scratch (no allocations allowed) --------
__device__ float d_AB[(size_t)NMAX * ABS];   // 64 MB
__device__ float d_Wab[GI * ABS];            // packed [W1a | pad | W1b | pad]
__device__ float d_Wc[GI * CPAD];            // W1c zero-padded to 160 cols
__device__ float d_Dt[9 * CPAD];             // dist table (+b1)
__device__ float d_Gt[8 * CPAD];             // genre table
__device__ float d_St[3 * CPAD];             // speaker table

// -------- packed f32x2 helpers --------
__device__ __forceinline__ void fma2(ull &d, ull a, ull b) {
    asm("fma.rn.f32x2 %0, %1, %2, %0;" : "+l"(d) : "l"(a), "l"(b));
}
__device__ __forceinline__ ull bcast2(float x) {
    ull r; asm("mov.b64 %0, {%1, %1};" : "=l"(r) : "f"(x)); return r;
}
__device__ __forceinline__ ull pk(float x, float y) {
    ull r; asm("mov.b64 %0, {%1, %2};" : "=l"(r) : "f"(x), "f"(y)); return r;
}
__device__ __forceinline__ float2 unpk(ull v) {
    float2 r; asm("mov.b64 {%0, %1}, %2;" : "=f"(r.x), "=f"(r.y) : "l"(v)); return r;
}

// ===================== weight prep =====================

__global__ void prep_weights(const float* __restrict__ W1) {
    int k = blockIdx.x;      // 0..GI-1
    int c = threadIdx.x;     // 0..319
    float v = 0.f;
    if (c < HID)                       v = W1[k * HID + c];
    else if (c >= CPAD && c < CPAD+HID) v = W1[(GI + k) * HID + (c - CPAD)];
    d_Wab[k * ABS + c] = v;
    if (c < CPAD)
        d_Wc[k * CPAD + c] = (c < HID) ? W1[(2 * GI + k) * HID + c] : 0.f;
}

__global__ void prep_tabs(const float* __restrict__ de, const float* __restrict__ ge,
                          const float* __restrict__ se, const float* __restrict__ W1,
                          const float* __restrict__ b1) {
    int c = threadIdx.x;     // 0..159
    for (int d = 0; d < 9; ++d) {
        float v = 0.f;
        if (c < HID) {
            v = b1[c];
            for (int t = 0; t < 20; ++t) v += de[d*20 + t] * W1[(3*GI + t) * HID + c];
        }
        d_Dt[d * CPAD + c] = v;
    }
    for (int g = 0; g < 8; ++g) {
        float v = 0.f;
        if (c < HID)
            for (int t = 0; t < 20; ++t) v += ge[g*20 + t] * W1[(3*GI + 20 + t) * HID + c];
        d_Gt[g * CPAD + c] = v;
    }
    for (int s = 0; s < 3; ++s) {
        float v = 0.f;
        if (c < HID)
            for (int t = 0; t < 20; ++t) v += se[s*20 + t] * W1[(3*GI + 40 + t) * HID + c];
        d_St[s * CPAD + c] = v;
    }
}

// ===================== AB precompute GEMM: [64 x 1220] @ [1220 x 320] =====================

__global__ __launch_bounds__(256) void gemm_ab(const float* __restrict__ g, int N) {
    __shared__ ull   Ws[KC * 160];   // 16 x 160 colpairs = 20 KB
    __shared__ float Qs[KC * 65];    // padded stride 65

    int t  = threadIdx.x;
    int tx = t & 15, ty = t >> 4;    // ty also serves as producer kk
    int ty4 = ty * 4;
    int n0 = blockIdx.x * 64;

    int pp = t >> 2, q = t & 3;
    int nrow = n0 + pp; if (nrow >= N) nrow = N - 1;
    const float* grow = g + (size_t)nrow * GI;

    ull acc[4][10];
    #pragma unroll
    for (int j = 0; j < 4; ++j)
        #pragma unroll
        for (int c = 0; c < 10; ++c) acc[j][c] = 0ull;

    const ull* Wab64 = (const ull*)d_Wab;   // row stride 160 colpairs

    for (int k0 = 0; k0 < GI; k0 += KC) {
        __syncthreads();
        // stage W chunk [16 x 320]
        {
            int k = k0 + ty;
            #pragma unroll
            for (int i = 0; i < 10; ++i) {
                ull w = 0ull;
                if (k < GI) w = Wab64[(size_t)k * 160 + tx + 16*i];
                Ws[ty * 160 + tx + 16*i] = w;
            }
        }
        // stage Q chunk [16 x 64] (transposed, stride 65)
        {
            int kb = k0 + 4*q;
            float4 v;
            if (kb + 3 < GI) v = *(const float4*)(grow + kb);
            else {
                v.x = (kb+0 < GI) ? grow[kb+0] : 0.f;
                v.y = (kb+1 < GI) ? grow[kb+1] : 0.f;
                v.z = (kb+2 < GI) ? grow[kb+2] : 0.f;
                v.w = (kb+3 < GI) ? grow[kb+3] : 0.f;
            }
            Qs[(4*q+0)*65 + pp] = v.x;
            Qs[(4*q+1)*65 + pp] = v.y;
            Qs[(4*q+2)*65 + pp] = v.z;
            Qs[(4*q+3)*65 + pp] = v.w;
        }
        __syncthreads();
        #pragma unroll
        for (int kk = 0; kk < KC; ++kk) {
            ull qq[4];
            #pragma unroll
            for (int j = 0; j < 4; ++j) qq[j] = bcast2(Qs[kk*65 + ty4 + j]);
            #pragma unroll
            for (int c = 0; c < 10; ++c) {
                ull w = Ws[kk*160 + tx + 16*c];
                #pragma unroll
                for (int j = 0; j < 4; ++j) fma2(acc[j][c], qq[j], w);
            }
        }
    }
    __syncthreads();

    ull* AB64 = (ull*)d_AB;   // row stride 160 colpairs
    #pragma unroll
    for (int j = 0; j < 4; ++j) {
        int n = n0 + ty4 + j;
        if (n < N) {
            #pragma unroll
            for (int c = 0; c < 10; ++c)
                AB64[(size_t)n * 160 + tx + 16*c] = acc[j][c];
        }
    }
}

// ===================== main: bilinear GEMM + fused MLP =====================

__global__ __launch_bounds__(256) void pair_main(
    const float* __restrict__ g,  const float* __restrict__ ms,
    const float* __restrict__ W2, const float* __restrict__ b2,
    const float* __restrict__ W3, const float* __restrict__ b3,
    const int* __restrict__ mid,  const int* __restrict__ aid,
    const int* __restrict__ did,  const int* __restrict__ gid,
    const int* __restrict__ sid,
    float* __restrict__ out, int P)
{
    extern __shared__ unsigned char smem_raw[];
    ull*   Ws   = (ull*)smem_raw;                                  // 16*80 ull = 10240 B
    float* QH   = (float*)(smem_raw + 10240);                      // Qs[16*65] then h1s[64*160]
    int*   sm_m = (int*)(smem_raw + 10240 + 64*CPAD*4);
    int*   sm_a = sm_m + 64;
    int*   sm_d = sm_a + 64;
    int*   sm_g = sm_d + 64;
    int*   sm_s = sm_g + 64;
    float* w3s  = (float*)(sm_s + 64);                             // [160]

    int t  = threadIdx.x;
    int tx = t & 15, ty = t >> 4;
    int ty4 = ty * 4;
    int p0 = blockIdx.x * 64;

    if (t < 64) {
        int p = p0 + t;
        int m = 0, a = 0, dd = 0, gg = 0, ss = 0;
        if (p < P) { m = mid[p]; a = aid[p]; dd = did[p]; gg = gid[p]; ss = sid[p]; }
        sm_m[t] = m; sm_a[t] = a; sm_d[t] = dd; sm_g[t] = gg; sm_s[t] = ss;
    }
    if (t < CPAD) w3s[t] = (t < HID) ? W3[t] : 0.f;
    __syncthreads();

    int pp = t >> 2, q = t & 3;
    const float* irow = g + (size_t)sm_m[pp] * GI;
    const float* jrow = g + (size_t)sm_a[pp] * GI;

    // ---- layer 1: bilinear (i*j) @ W1c over K=1220 ----
    ull acc[4][5];
    #pragma unroll
    for (int j = 0; j < 4; ++j)
        #pragma unroll
        for (int c = 0; c < 5; ++c) acc[j][c] = 0ull;

    const ull* Wc64 = (const ull*)d_Wc;   // row stride 80 colpairs

    for (int k0 = 0; k0 < GI; k0 += KC) {
        __syncthreads();
        {
            int k = k0 + ty;
            #pragma unroll
            for (int i = 0; i < 5; ++i) {
                ull w = 0ull;
                if (k < GI) w = Wc64[(size_t)k * 80 + tx + 16*i];
                Ws[ty * 80 + tx + 16*i] = w;
            }
        }
        {
            int kb = k0 + 4*q;
            float4 x, y;
            if (kb + 3 < GI) {
                x = *(const float4*)(irow + kb);
                y = *(const float4*)(jrow + kb);
            } else {
                x.x = (kb+0 < GI) ? irow[kb+0] : 0.f;  y.x = (kb+0 < GI) ? jrow[kb+0] : 0.f;
                x.y = (kb+1 < GI) ? irow[kb+1] : 0.f;  y.y = (kb+1 < GI) ? jrow[kb+1] : 0.f;
                x.z = (kb+2 < GI) ? irow[kb+2] : 0.f;  y.z = (kb+2 < GI) ? jrow[kb+2] : 0.f;
                x.w = (kb+3 < GI) ? irow[kb+3] : 0.f;  y.w = (kb+3 < GI) ? jrow[kb+3] : 0.f;
            }
            QH[(4*q+0)*65 + pp] = x.x * y.x;
            QH[(4*q+1)*65 + pp] = x.y * y.y;
            QH[(4*q+2)*65 + pp] = x.z * y.z;
            QH[(4*q+3)*65 + pp] = x.w * y.w;
        }
        __syncthreads();
        #pragma unroll
        for (int kk = 0; kk < KC; ++kk) {
            ull qq[4];
            #pragma unroll
            for (int j = 0; j < 4; ++j) qq[j] = bcast2(QH[kk*65 + ty4 + j]);
            #pragma unroll
            for (int c = 0; c < 5; ++c) {
                ull w = Ws[kk*80 + tx + 16*c];
                #pragma unroll
                for (int j = 0; j < 4; ++j) fma2(acc[j][c], qq[j], w);
            }
        }
    }
    __syncthreads();

    // ---- epilogue 1: h1 = relu(bilinear + AB[m] + AB[a] + Dt + Gt + St) -> SMEM ----
    {
        const float2* AB2 = (const float2*)d_AB;   // row stride 160 float2
        const float2* Dt2 = (const float2*)d_Dt;   // row stride 80 float2
        const float2* Gt2 = (const float2*)d_Gt;
        const float2* St2 = (const float2*)d_St;
        #pragma unroll
        for (int j = 0; j < 4; ++j) {
            int r = ty4 + j;
            const float2* am = AB2 + (size_t)sm_m[r] * 160;
            const float2* bm = AB2 + (size_t)sm_a[r] * 160 + 80;
            const float2* dp = Dt2 + sm_d[r] * 80;
            const float2* gp = Gt2 + sm_g[r] * 80;
            const float2* sp = St2 + sm_s[r] * 80;
            #pragma unroll
            for (int c = 0; c < 5; ++c) {
                int cp = tx + 16*c;
                float2 v  = unpk(acc[j][c]);
                float2 t1 = am[cp], t2 = bm[cp], t3 = dp[cp], t4 = gp[cp], t5 = sp[cp];
                v.x = fmaxf(v.x + t1.x + t2.x + t3.x + t4.x + t5.x, 0.f);
                v.y = fmaxf(v.y + t1.y + t2.y + t3.y + t4.y + t5.y, 0.f);
                *(float2*)(QH + r * CPAD + 2*cp) = v;
            }
        }
    }

    // ---- layer 2: h2pre = h1 @ W2 ----
    ull acc2[4][5];
    #pragma unroll
    for (int j = 0; j < 4; ++j)
        #pragma unroll
        for (int c = 0; c < 5; ++c) acc2[j][c] = 0ull;

    for (int k0 = 0; k0 < CPAD; k0 += KC) {   // 10 chunks (k>=150 is zero-padded)
        __syncthreads();
        {
            int k = k0 + ty;
            #pragma unroll
            for (int i = 0; i < 5; ++i) {
                int cp = tx + 16*i, c0 = 2*cp;
                ull w = 0ull;
                if (k < HID) {
                    float lo = (c0   < HID) ? W2[k*HID + c0    ] : 0.f;
                    float hi = (c0+1 < HID) ? W2[k*HID + c0 + 1] : 0.f;
                    w = pk(lo, hi);
                }
                Ws[ty * 80 + cp] = w;
            }
        }
        __syncthreads();
        #pragma unroll
        for (int kk = 0; kk < KC; ++kk) {
            ull qq[4];
            #pragma unroll
            for (int j = 0; j < 4; ++j) qq[j] = bcast2(QH[(ty4+j)*CPAD + k0 + kk]);
            #pragma unroll
            for (int c = 0; c < 5; ++c) {
                ull w = Ws[kk*80 + tx + 16*c];
                #pragma unroll
                for (int j = 0; j < 4; ++j) fma2(acc2[j][c], qq[j], w);
            }
        }
    }

    // ---- epilogue 2: relu(h2pre + b2) @ W3 + b3 + ms[m] + ms[a] ----
    float b3v = b3[0];
    float part[4] = {0.f, 0.f, 0.f, 0.f};
    #pragma unroll
    for (int c = 0; c < 5; ++c) {
        int c0 = 2 * (tx + 16*c);
        float w3a = w3s[c0], w3b = w3s[c0 + 1];
        float b2a = (c0   < HID) ? b2[c0    ] : 0.f;
        float b2b = (c0+1 < HID) ? b2[c0 + 1] : 0.f;
        #pragma unroll
        for (int j = 0; j < 4; ++j) {
            float2 v = unpk(acc2[j][c]);
            part[j] += fmaxf(v.x + b2a, 0.f) * w3a + fmaxf(v.y + b2b, 0.f) * w3b;
        }
    }
    #pragma unroll
    for (int j = 0; j < 4; ++j) {
        #pragma unroll
        for (int off = 8; off > 0; off >>= 1)
            part[j] += __shfl_xor_sync(0xffffffffu, part[j], off);
    }
    if (tx == 0) {
        #pragma unroll
        for (int j = 0; j < 4; ++j) {
            int p = p0 + ty4 + j;
            if (p < P)
                out[p] = part[j] + b3v + ms[sm_m[ty4 + j]] + ms[sm_a[ty4 + j]];
        }
    }
}

// ===================== launch =====================

extern "C" void kernel_launch(void* const* d_in, const int* in_sizes, int n_in,
                              void* d_out, int out_size)
{
    const float* g_i = (const float*)d_in[0];
    const float* ms  = (const float*)d_in[1];
    const float* de  = (const float*)d_in[2];
    const float* ge  = (const float*)d_in[3];
    const float* se  = (const float*)d_in[4];
    const float* W1  = (const float*)d_in[5];
    const float* b1  = (const float*)d_in[6];
    const float* W2  = (const float*)d_in[7];
    const float* b2  = (const float*)d_in[8];
    const float* W3  = (const float*)d_in[9];
    const float* b3  = (const float*)d_in[10];
    const int*   mid = (const int*)d_in[11];
    const int*   aid = (const int*)d_in[12];
    const int*   did = (const int*)d_in[13];
    const int*   gid = (const int*)d_in[14];
    const int*   sid = (const int*)d_in[15];

    int N = in_sizes[0] / GI;
    if (N > NMAX) N = NMAX;
    int P = in_sizes[11];
    float* out = (float*)d_out;

    prep_weights<<<GI, 320>>>(W1);
    prep_tabs<<<1, CPAD>>>(de, ge, se, W1, b1);
    gemm_ab<<<(N + 63) / 64, 256>>>(g_i, N);

    int smem = 10240 + 64*CPAD*4 + 5*64*4 + CPAD*4;   // 53120 B
    cudaFuncSetAttribute(pair_main, cudaFuncAttributeMaxDynamicSharedMemorySize, smem);
    pair_main<<<(P + 63) / 64, 256, smem>>>(g_i, ms, W2, b2, W3, b3,
                                            mid, aid, did, gid, sid, out, P);
}

// round 3
// speedup vs baseline: 1.0010x; 1.0005x over previous
#include <cuda_runtime.h>

// PairwiseScore — fp32 baseline with algebraic decomposition + packed f32x2 FMA.
//
// pairs@W1 = i_g@W1a + j_g@W1b + (i_g*j_g)@W1c + phi@W1d
//   - AB[n]  : per-mention precompute of g_i[n]@W1a (cols 0..149) and g_i[n]@W1b (cols 160..309)
//   - Dt/Gt/St: tiny phi lookup tables (b1 folded into Dt)
//   - main kernel: bilinear GEMM per 64-pair tile + fused 2-layer MLP epilogue.

typedef unsigned long long ull;

#define GI   1220
#define HID  150
#define NMAX 50000
#define CPAD 160      // padded hidden width (cols 150..159 are zero)
#define ABS  320      // AB row stride in floats (A part @0, B part @160)
#define KC   16       // K-chunk

// -------- device scratch (no allocations allowed) --------
__device__ float d_AB[(size_t)NMAX * ABS];   // 64 MB
__device__ float d_Wab[GI * ABS];            // packed [W1a | pad | W1b | pad]
__device__ float d_Wc[GI * CPAD];            // W1c zero-padded to 160 cols
__device__ float d_Dt[9 * CPAD];             // dist table (+b1)
__device__ float d_Gt[8 * CPAD];             // genre table
__device__ float d_St[3 * CPAD];             // speaker table

// -------- packed f32x2 helpers --------
__device__ __forceinline__ void fma2(ull &d, ull a, ull b) {
    asm("fma.rn.f32x2 %0, %1, %2, %0;" : "+l"(d) : "l"(a), "l"(b));
}
__device__ __forceinline__ ull bcast2(float x) {
    ull r; asm("mov.b64 %0, {%1, %1};" : "=l"(r) : "f"(x)); return r;
}
__device__ __forceinline__ ull pk(float x, float y) {
    ull r; asm("mov.b64 %0, {%1, %2};" : "=l"(r) : "f"(x), "f"(y)); return r;
}
__device__ __forceinline__ float2 unpk(ull v) {
    float2 r; asm("mov.b64 {%0, %1}, %2;" : "=f"(r.x), "=f"(r.y) : "l"(v)); return r;
}

// ===================== weight prep =====================

__global__ void prep_weights(const float* __restrict__ W1) {
    int k = blockIdx.x;      // 0..GI-1
    int c = threadIdx.x;     // 0..319
    float v = 0.f;
    if (c < HID)                       v = W1[k * HID + c];
    else if (c >= CPAD && c < CPAD+HID) v = W1[(GI + k) * HID + (c - CPAD)];
    d_Wab[k * ABS + c] = v;
    if (c < CPAD)
        d_Wc[k * CPAD + c] = (c < HID) ? W1[(2 * GI + k) * HID + c] : 0.f;
}

__global__ void prep_tabs(const float* __restrict__ de, const float* __restrict__ ge,
                          const float* __restrict__ se, const float* __restrict__ W1,
                          const float* __restrict__ b1) {
    int c = threadIdx.x;     // 0..159
    for (int d = 0; d < 9; ++d) {
        float v = 0.f;
        if (c < HID) {
            v = b1[c];
            for (int t = 0; t < 20; ++t) v += de[d*20 + t] * W1[(3*GI + t) * HID + c];
        }
        d_Dt[d * CPAD + c] = v;
    }
    for (int g = 0; g < 8; ++g) {
        float v = 0.f;
        if (c < HID)
            for (int t = 0; t < 20; ++t) v += ge[g*20 + t] * W1[(3*GI + 20 + t) * HID + c];
        d_Gt[g * CPAD + c] = v;
    }
    for (int s = 0; s < 3; ++s) {
        float v = 0.f;
        if (c < HID)
            for (int t = 0; t < 20; ++t) v += se[s*20 + t] * W1[(3*GI + 40 + t) * HID + c];
        d_St[s * CPAD + c] = v;
    }
}

// ===================== AB precompute GEMM: [64 x 1220] @ [1220 x 320] =====================

__global__ __launch_bounds__(256) void gemm_ab(const float* __restrict__ g, int N) {
    __shared__ ull   Ws[KC * 160];   // 16 x 160 colpairs = 20 KB
    __shared__ float Qs[KC * 65];    // padded stride 65

    int t  = threadIdx.x;
    int tx = t & 15, ty = t >> 4;    // ty also serves as producer kk
    int ty4 = ty * 4;
    int n0 = blockIdx.x * 64;

    int pp = t >> 2, q = t & 3;
    int nrow = n0 + pp; if (nrow >= N) nrow = N - 1;
    const float* grow = g + (size_t)nrow * GI;

    ull acc[4][10];
    #pragma unroll
    for (int j = 0; j < 4; ++j)
        #pragma unroll
        for (int c = 0; c < 10; ++c) acc[j][c] = 0ull;

    const ull* Wab64 = (const ull*)d_Wab;   // row stride 160 colpairs

    for (int k0 = 0; k0 < GI; k0 += KC) {
        __syncthreads();
        // stage W chunk [16 x 320]
        {
            int k = k0 + ty;
            #pragma unroll
            for (int i = 0; i < 10; ++i) {
                ull w = 0ull;
                if (k < GI) w = Wab64[(size_t)k * 160 + tx + 16*i];
                Ws[ty * 160 + tx + 16*i] = w;
            }
        }
        // stage Q chunk [16 x 64] (transposed, stride 65)
        {
            int kb = k0 + 4*q;
            float4 v;
            if (kb + 3 < GI) v = *(const float4*)(grow + kb);
            else {
                v.x = (kb+0 < GI) ? grow[kb+0] : 0.f;
                v.y = (kb+1 < GI) ? grow[kb+1] : 0.f;
                v.z = (kb+2 < GI) ? grow[kb+2] : 0.f;
                v.w = (kb+3 < GI) ? grow[kb+3] : 0.f;
            }
            Qs[(4*q+0)*65 + pp] = v.x;
            Qs[(4*q+1)*65 + pp] = v.y;
            Qs[(4*q+2)*65 + pp] = v.z;
            Qs[(4*q+3)*65 + pp] = v.w;
        }
        __syncthreads();
        #pragma unroll
        for (int kk = 0; kk < KC; ++kk) {
            ull qq[4];
            #pragma unroll
            for (int j = 0; j < 4; ++j) qq[j] = bcast2(Qs[kk*65 + ty4 + j]);
            #pragma unroll
            for (int c = 0; c < 10; ++c) {
                ull w = Ws[kk*160 + tx + 16*c];
                #pragma unroll
                for (int j = 0; j < 4; ++j) fma2(acc[j][c], qq[j], w);
            }
        }
    }
    __syncthreads();

    ull* AB64 = (ull*)d_AB;   // row stride 160 colpairs
    #pragma unroll
    for (int j = 0; j < 4; ++j) {
        int n = n0 + ty4 + j;
        if (n < N) {
            #pragma unroll
            for (int c = 0; c < 10; ++c)
                AB64[(size_t)n * 160 + tx + 16*c] = acc[j][c];
        }
    }
}

// ===================== main: bilinear GEMM + fused MLP =====================

__global__ __launch_bounds__(256) void pair_main(
    const float* __restrict__ g,  const float* __restrict__ ms,
    const float* __restrict__ W2, const float* __restrict__ b2,
    const float* __restrict__ W3, const float* __restrict__ b3,
    const int* __restrict__ mid,  const int* __restrict__ aid,
    const int* __restrict__ did,  const int* __restrict__ gid,
    const int* __restrict__ sid,
    float* __restrict__ out, int P)
{
    extern __shared__ unsigned char smem_raw[];
    ull*   Ws   = (ull*)smem_raw;                                  // 16*80 ull = 10240 B
    float* QH   = (float*)(smem_raw + 10240);                      // Qs[16*65] then h1s[64*160]
    int*   sm_m = (int*)(smem_raw + 10240 + 64*CPAD*4);
    int*   sm_a = sm_m + 64;
    int*   sm_d = sm_a + 64;
    int*   sm_g = sm_d + 64;
    int*   sm_s = sm_g + 64;
    float* w3s  = (float*)(sm_s + 64);                             // [160]

    int t  = threadIdx.x;
    int tx = t & 15, ty = t >> 4;
    int ty4 = ty * 4;
    int p0 = blockIdx.x * 64;

    if (t < 64) {
        int p = p0 + t;
        int m = 0, a = 0, dd = 0, gg = 0, ss = 0;
        if (p < P) { m = mid[p]; a = aid[p]; dd = did[p]; gg = gid[p]; ss = sid[p]; }
        sm_m[t] = m; sm_a[t] = a; sm_d[t] = dd; sm_g[t] = gg; sm_s[t] = ss;
    }
    if (t < CPAD) w3s[t] = (t < HID) ? W3[t] : 0.f;
    __syncthreads();

    int pp = t >> 2, q = t & 3;
    const float* irow = g + (size_t)sm_m[pp] * GI;
    const float* jrow = g + (size_t)sm_a[pp] * GI;

    // ---- layer 1: bilinear (i*j) @ W1c over K=1220 ----
    ull acc[4][5];
    #pragma unroll
    for (int j = 0; j < 4; ++j)
        #pragma unroll
        for (int c = 0; c < 5; ++c) acc[j][c] = 0ull;

    const ull* Wc64 = (const ull*)d_Wc;   // row stride 80 colpairs

    for (int k0 = 0; k0 < GI; k0 += KC) {
        __syncthreads();
        {
            int k = k0 + ty;
            #pragma unroll
            for (int i = 0; i < 5; ++i) {
                ull w = 0ull;
                if (k < GI) w = Wc64[(size_t)k * 80 + tx + 16*i];
                Ws[ty * 80 + tx + 16*i] = w;
            }
        }
        {
            int kb = k0 + 4*q;
            float4 x, y;
            if (kb + 3 < GI) {
                x = *(const float4*)(irow + kb);
                y = *(const float4*)(jrow + kb);
            } else {
                x.x = (kb+0 < GI) ? irow[kb+0] : 0.f;  y.x = (kb+0 < GI) ? jrow[kb+0] : 0.f;
                x.y = (kb+1 < GI) ? irow[kb+1] : 0.f;  y.y = (kb+1 < GI) ? jrow[kb+1] : 0.f;
                x.z = (kb+2 < GI) ? irow[kb+2] : 0.f;  y.z = (kb+2 < GI) ? jrow[kb+2] : 0.f;
                x.w = (kb+3 < GI) ? irow[kb+3] : 0.f;  y.w = (kb+3 < GI) ? jrow[kb+3] : 0.f;
            }
            QH[(4*q+0)*65 + pp] = x.x * y.x;
            QH[(4*q+1)*65 + pp] = x.y * y.y;
            QH[(4*q+2)*65 + pp] = x.z * y.z;
            QH[(4*q+3)*65 + pp] = x.w * y.w;
        }
        __syncthreads();
        #pragma unroll
        for (int kk = 0; kk < KC; ++kk) {
            ull qq[4];
            #pragma unroll
            for (int j = 0; j < 4; ++j) qq[j] = bcast2(QH[kk*65 + ty4 + j]);
            #pragma unroll
            for (int c = 0; c < 5; ++c) {
                ull w = Ws[kk*80 + tx + 16*c];
                #pragma unroll
                for (int j = 0; j < 4; ++j) fma2(acc[j][c], qq[j], w);
            }
        }
    }
    __syncthreads();

    // ---- epilogue 1: h1 = relu(bilinear + AB[m] + AB[a] + Dt + Gt + St) -> SMEM ----
    {
        const float2* AB2 = (const float2*)d_AB;   // row stride 160 float2
        const float2* Dt2 = (const float2*)d_Dt;   // row stride 80 float2
        const float2* Gt2 = (const float2*)d_Gt;
        const float2* St2 = (const float2*)d_St;
        #pragma unroll
        for (int j = 0; j < 4; ++j) {
            int r = ty4 + j;
            const float2* am = AB2 + (size_t)sm_m[r] * 160;
            const float2* bm = AB2 + (size_t)sm_a[r] * 160 + 80;
            const float2* dp = Dt2 + sm_d[r] * 80;
            const float2* gp = Gt2 + sm_g[r] * 80;
            const float2* sp = St2 + sm_s[r] * 80;
            #pragma unroll
            for (int c = 0; c < 5; ++c) {
                int cp = tx + 16*c;
                float2 v  = unpk(acc[j][c]);
                float2 t1 = am[cp], t2 = bm[cp], t3 = dp[cp], t4 = gp[cp], t5 = sp[cp];
                v.x = fmaxf(v.x + t1.x + t2.x + t3.x + t4.x + t5.x, 0.f);
                v.y = fmaxf(v.y + t1.y + t2.y + t3.y + t4.y + t5.y, 0.f);
                *(float2*)(QH + r * CPAD + 2*cp) = v;
            }
        }
    }

    // ---- layer 2: h2pre = h1 @ W2 ----
    ull acc2[4][5];
    #pragma unroll
    for (int j = 0; j < 4; ++j)
        #pragma unroll
        for (int c = 0; c < 5; ++c) acc2[j][c] = 0ull;

    for (int k0 = 0; k0 < CPAD; k0 += KC) {   // 10 chunks (k>=150 is zero-padded)
        __syncthreads();
        {
            int k = k0 + ty;
            #pragma unroll
            for (int i = 0; i < 5; ++i) {
                int cp = tx + 16*i, c0 = 2*cp;
                ull w = 0ull;
                if (k < HID) {
                    float lo = (c0   < HID) ? W2[k*HID + c0    ] : 0.f;
                    float hi = (c0+1 < HID) ? W2[k*HID + c0 + 1] : 0.f;
                    w = pk(lo, hi);
                }
                Ws[ty * 80 + cp] = w;
            }
        }
        __syncthreads();
        #pragma unroll
        for (int kk = 0; kk < KC; ++kk) {
            ull qq[4];
            #pragma unroll
            for (int j = 0; j < 4; ++j) qq[j] = bcast2(QH[(ty4+j)*CPAD + k0 + kk]);
            #pragma unroll
            for (int c = 0; c < 5; ++c) {
                ull w = Ws[kk*80 + tx + 16*c];
                #pragma unroll
                for (int j = 0; j < 4; ++j) fma2(acc2[j][c], qq[j], w);
            }
        }
    }

    // ---- epilogue 2: relu(h2pre + b2) @ W3 + b3 + ms[m] + ms[a] ----
    float b3v = b3[0];
    float part[4] = {0.f, 0.f, 0.f, 0.f};
    #pragma unroll
    for (int c = 0; c < 5; ++c) {
        int c0 = 2 * (tx + 16*c);
        float w3a = w3s[c0], w3b = w3s[c0 + 1];
        float b2a = (c0   < HID) ? b2[c0    ] : 0.f;
        float b2b = (c0+1 < HID) ? b2[c0 + 1] : 0.f;
        #pragma unroll
        for (int j = 0; j < 4; ++j) {
            float2 v = unpk(acc2[j][c]);
            part[j] += fmaxf(v.x + b2a, 0.f) * w3a + fmaxf(v.y + b2b, 0.f) * w3b;
        }
    }
    #pragma unroll
    for (int j = 0; j < 4; ++j) {
        #pragma unroll
        for (int off = 8; off > 0; off >>= 1)
            part[j] += __shfl_xor_sync(0xffffffffu, part[j], off);
    }
    if (tx == 0) {
        #pragma unroll
        for (int j = 0; j < 4; ++j) {
            int p = p0 + ty4 + j;
            if (p < P)
                out[p] = part[j] + b3v + ms[sm_m[ty4 + j]] + ms[sm_a[ty4 + j]];
        }
    }
}

// ===================== launch =====================

extern "C" void kernel_launch(void* const* d_in, const int* in_sizes, int n_in,
                              void* d_out, int out_size)
{
    const float* g_i = (const float*)d_in[0];
    const float* ms  = (const float*)d_in[1];
    const float* de  = (const float*)d_in[2];
    const float* ge  = (const float*)d_in[3];
    const float* se  = (const float*)d_in[4];
    const float* W1  = (const float*)d_in[5];
    const float* b1  = (const float*)d_in[6];
    const float* W2  = (const float*)d_in[7];
    const float* b2  = (const float*)d_in[8];
    const float* W3  = (const float*)d_in[9];
    const float* b3  = (const float*)d_in[10];
    const int*   mid = (const int*)d_in[11];
    const int*   aid = (const int*)d_in[12];
    const int*   did = (const int*)d_in[13];
    const int*   gid = (const int*)d_in[14];
    const int*   sid = (const int*)d_in[15];

    int N = in_sizes[0] / GI;
    if (N > NMAX) N = NMAX;
    int P = in_sizes[11];
    float* out = (float*)d_out;

    prep_weights<<<GI, 320>>>(W1);
    prep_tabs<<<1, CPAD>>>(de, ge, se, W1, b1);
    gemm_ab<<<(N + 63) / 64, 256>>>(g_i, N);

    int smem = 10240 + 64*CPAD*4 + 5*64*4 + CPAD*4;   // 53120 B
    cudaFuncSetAttribute(pair_main, cudaFuncAttributeMaxDynamicSharedMemorySize, smem);
    pair_main<<<(P + 63) / 64, 256, smem>>>(g_i, ms, W2, b2, W3, b3,
                                            mid, aid, did, gid, sid, out, P);
}